// round 12
// baseline (speedup 1.0000x reference)
#include <cuda_runtime.h>
#include <cuda_bf16.h>
#include <cstdint>

// BS=64, G=64, L=100, D=64. NG=4096 groups.
// softmax shift-invariance: V_last/V_avg/b cancel => attn = softmax_l(seqs[l].(W2@p)).
// lens, W1, W3, b unused.
// attn: R6 (20.6us DRAM-bound). MLP v2: 8-row x 4-col tiles, 4-way K-split,
// dup-u64 operands, Wl1 staged mid-kernel into dead regions (counts FIXED).

#define NG   4096
#define L    100
#define D    64

typedef unsigned long long u64;

__device__ float g_weighted[NG * D];

// ---------------------------------------------------------------------------
// helpers
// ---------------------------------------------------------------------------
__device__ __forceinline__ void cp16(unsigned int s_addr, const void* g) {
    asm volatile("cp.async.cg.shared.global [%0], [%1], 16;\n" :: "r"(s_addr), "l"(g));
}
#define CP_COMMIT() asm volatile("cp.async.commit_group;\n" ::: "memory")
#define CP_WAIT(n)  asm volatile("cp.async.wait_group %0;\n" :: "n"(n) : "memory")

__device__ __forceinline__ u64 pk2(float v) {
    u64 r; asm("mov.b64 %0, {%1, %1};" : "=l"(r) : "f"(v)); return r;
}
__device__ __forceinline__ void fma2(u64& d, u64 a, u64 b) {
    asm("fma.rn.f32x2 %0, %1, %2, %0;" : "+l"(d) : "l"(a), "l"(b));
}
__device__ __forceinline__ void add2(u64& d, u64 a) {
    asm("add.rn.f32x2 %0, %0, %1;" : "+l"(d) : "l"(a));
}
__device__ __forceinline__ float2 unpk(u64 v) {
    float2 r; asm("mov.b64 {%0, %1}, %2;" : "=f"(r.x), "=f"(r.y) : "l"(v)); return r;
}
__device__ __forceinline__ u64 pkpair(float lo, float hi) {
    u64 r; asm("mov.b64 %0, {%1, %2};" : "=l"(r) : "f"(lo), "f"(hi)); return r;
}

// ---------------------------------------------------------------------------
// Kernel 1: attention pooling, 2 groups per block, 256 threads. (R6, unchanged)
// ---------------------------------------------------------------------------
__global__ __launch_bounds__(256) void attn_kernel(
    const float* __restrict__ seqs, const float* __restrict__ W2,
    const float* __restrict__ p)
{
    __shared__ float w2s[D * 65];
    __shared__ float ps[D];
    __shared__ float q_s[D];
    __shared__ float attn_sh[2][104];
    __shared__ float red[2][4];
    __shared__ float part4[2][4][16][4];

    const int tid  = threadIdx.x;
    const int half = tid >> 7;
    const int t    = tid & 127;
    const int g    = blockIdx.x * 2 + half;
    const int w    = t >> 5;
    const int lane = t & 31;
    const int c4   = t & 15;
    const int grp  = t >> 4;

    const float4* src = (const float4*)(seqs + (size_t)g * (L * D));
    float4 r[13];
#pragma unroll
    for (int k = 0; k < 13; ++k) {
        int idx = t + k * 128;
        if (idx < L * (D / 4)) r[k] = __ldg(src + idx);
        else                   r[k] = make_float4(0.f, 0.f, 0.f, 0.f);
    }

#pragma unroll
    for (int i = 0; i < 4; ++i) {
        int idx = tid + i * 256;
        float4 wv = __ldg((const float4*)W2 + idx);
        int row = idx >> 4, c = idx & 15;
        float* dst = &w2s[row * 65 + c * 4];
        dst[0] = wv.x; dst[1] = wv.y; dst[2] = wv.z; dst[3] = wv.w;
    }
    if (tid >= 64 && tid < 128) ps[tid - 64] = __ldg(p + tid - 64);
    __syncthreads();

    if (tid < D) {
        float acc = 0.f;
        const float* row = &w2s[tid * 65];
#pragma unroll 16
        for (int e = 0; e < D; ++e) acc += row[e] * ps[e];
        q_s[tid] = acc;
    }
    __syncthreads();

    const float4 q4 = *(const float4*)&q_s[c4 * 4];
#pragma unroll
    for (int k = 0; k < 13; ++k) {
        float v = r[k].x * q4.x + r[k].y * q4.y + r[k].z * q4.z + r[k].w * q4.w;
        v += __shfl_xor_sync(0xffffffffu, v, 1);
        v += __shfl_xor_sync(0xffffffffu, v, 2);
        v += __shfl_xor_sync(0xffffffffu, v, 4);
        v += __shfl_xor_sync(0xffffffffu, v, 8);
        int row = grp + 8 * k;
        if (c4 == 0 && row < L) attn_sh[half][row] = v;
    }
    __syncthreads();

    float v = (t < L) ? attn_sh[half][t] : -1e30f;
    float m = v;
#pragma unroll
    for (int o = 16; o > 0; o >>= 1) m = fmaxf(m, __shfl_xor_sync(0xffffffffu, m, o));
    if (lane == 0) red[half][w] = m;
    __syncthreads();
    float vmax = fmaxf(fmaxf(red[half][0], red[half][1]),
                       fmaxf(red[half][2], red[half][3]));
    __syncthreads();

    float e = (t < L) ? __expf(v - vmax) : 0.f;
    float sv = e;
#pragma unroll
    for (int o = 16; o > 0; o >>= 1) sv += __shfl_xor_sync(0xffffffffu, sv, o);
    if (lane == 0) red[half][w] = sv;
    __syncthreads();
    float inv = 1.f / (red[half][0] + red[half][1] + red[half][2] + red[half][3]);
    if (t < L) attn_sh[half][t] = e * inv;
    else if (t < 104) attn_sh[half][t] = 0.f;
    __syncthreads();

    float4 p4 = make_float4(0.f, 0.f, 0.f, 0.f);
#pragma unroll
    for (int k = 0; k < 13; ++k) {
        float a = attn_sh[half][grp + 8 * k];
        p4.x += a * r[k].x; p4.y += a * r[k].y;
        p4.z += a * r[k].z; p4.w += a * r[k].w;
    }
    p4.x += __shfl_xor_sync(0xffffffffu, p4.x, 16);
    p4.y += __shfl_xor_sync(0xffffffffu, p4.y, 16);
    p4.z += __shfl_xor_sync(0xffffffffu, p4.z, 16);
    p4.w += __shfl_xor_sync(0xffffffffu, p4.w, 16);
    if (lane < 16) *(float4*)&part4[half][w][lane][0] = p4;
    __syncthreads();
    if (t < D) {
        int ci = t >> 2, comp = t & 3;
        float sum = part4[half][0][ci][comp] + part4[half][1][ci][comp]
                  + part4[half][2][ci][comp] + part4[half][3][ci][comp];
        g_weighted[g * D + t] = sum;
    }
}

// ---------------------------------------------------------------------------
// MLP v2. 128 blocks x 512 threads, 32 rows/block.
// warp wr: rt = wr&3 (rows rt*8..+8), kh = wr>>2 (K-quarter). lane: cols lane*4..+4.
// smem byte map (212992 total):
//  [0,32768)       wq (stage1)          | wl1 d0..95  (staged after st1; 49152 B)
//  [32768,49152)   xdup u64[32][64]     |   "
//  [49152,65536)   h0dup rows 0..15     | wl1 d96..127 (staged after st2; 16384 B)
//  [65536,81920)   h0dup rows 16..31    | P1 slice stage2
//  [81920,147456)  wl0                  | P1 slice stage3
//  [147456,180224) h1dup u64[32][128]   | P1 slice stage1
//  [180224,196608) P0 u64[32][64]
//  [196608,212992) h0pair u64[32][64]
// ---------------------------------------------------------------------------
template<int KQ>
__device__ __forceinline__ void mlp_compute(
    const float* __restrict__ ws, const u64* __restrict__ xin, int xstride,
    int dbase, int r0, int c0, u64 (&acc)[8][2])
{
#pragma unroll
    for (int i = 0; i < 8; ++i) { acc[i][0] = 0ull; acc[i][1] = 0ull; }
#pragma unroll
    for (int i = 0; i < KQ; i += 2) {
        const int dd = dbase + i;
        float4 wv0 = *(const float4*)&ws[dd * 128 + c0];
        float4 wv1 = *(const float4*)&ws[(dd + 1) * 128 + c0];
        u64 w0l = *(const u64*)&wv0.x, w0h = *(const u64*)&wv0.z;
        u64 w1l = *(const u64*)&wv1.x, w1h = *(const u64*)&wv1.z;
#pragma unroll
        for (int hrow = 0; hrow < 2; ++hrow) {
            ulonglong2 xp[4];
#pragma unroll
            for (int rr = 0; rr < 4; ++rr)
                xp[rr] = *(const ulonglong2*)&xin[(r0 + hrow * 4 + rr) * xstride + dd];
#pragma unroll
            for (int rr = 0; rr < 4; ++rr) {
                const int row = hrow * 4 + rr;
                fma2(acc[row][0], xp[rr].x, w0l);
                fma2(acc[row][1], xp[rr].x, w0h);
                fma2(acc[row][0], xp[rr].y, w1l);
                fma2(acc[row][1], xp[rr].y, w1h);
            }
        }
    }
}

__global__ __launch_bounds__(512) void mlp_kernel(
    const float* __restrict__ Wq,  const float* __restrict__ Wl0,
    const float* __restrict__ bl0, const float* __restrict__ Wl1,
    const float* __restrict__ bl1, float* __restrict__ out)
{
    extern __shared__ char smem[];
    float* wqf    = (float*)(smem);
    u64*   xdup   = (u64*)(smem + 32768);
    u64*   h0dup  = (u64*)(smem + 49152);
    float* wl0f   = (float*)(smem + 81920);
    u64*   h1dup  = (u64*)(smem + 147456);
    u64*   P0     = (u64*)(smem + 180224);
    u64*   h0pair = (u64*)(smem + 196608);
    float* wl1f   = (float*)(smem);                 // stage3 weights [0,65536)
    u64*   P1s1   = (u64*)(smem + 147456);          // aliases h1dup (free in st1)
    u64*   P1s2   = (u64*)(smem + 65536);           // h0dup rows16-31 (dead post st2 compute)
    u64*   P1s3   = (u64*)(smem + 81920);           // wl0 (dead post st2)

    const int t    = threadIdx.x;
    const int row0 = blockIdx.x * 32;
    const unsigned int sb = (unsigned int)__cvta_generic_to_shared(smem);

    // ---- initial staging: C1 = wq (2048 f4), C2 = wl0 (4096 f4) ----
#pragma unroll
    for (int i = 0; i < 4; ++i) {
        int idx = t + i * 512;
        cp16(sb + idx * 16, (const float4*)Wq + idx);
    }
    CP_COMMIT();
#pragma unroll
    for (int i = 0; i < 8; ++i) {
        int idx = t + i * 512;
        cp16(sb + 81920 + idx * 16, (const float4*)Wl0 + idx);
    }
    CP_COMMIT();

    // ---- xdup: duplicated store of g_weighted rows ----
    {
        float4 xv = __ldg((const float4*)(g_weighted + (size_t)row0 * D) + t);
        int row = t >> 4, c = (t & 15) * 4;
        xdup[row * 64 + c + 0] = pk2(xv.x);
        xdup[row * 64 + c + 1] = pk2(xv.y);
        xdup[row * 64 + c + 2] = pk2(xv.z);
        xdup[row * 64 + c + 3] = pk2(xv.w);
    }
    CP_WAIT(1);            // wq done
    __syncthreads();

    const int wr   = t >> 5;
    const int rt   = wr & 3;
    const int kh   = wr >> 2;
    const int lane = t & 31;
    const int r0   = rt * 8;
    const int c0   = lane * 4;

    u64 acc[8][2];

    // ================= stage 1: h0 = X @ Wq (K=64) =================
    mlp_compute<16>(wqf, xdup, 64, kh * 16, r0, c0, acc);
    __syncthreads();                                  // wq/xdup dead now

    // stage wl1 d0..95: 96*128 floats = 3072 f4 -> [0,49152)
#pragma unroll
    for (int i = 0; i < 6; ++i) {
        int idx = t + i * 512;                        // < 3072
        cp16(sb + idx * 16, (const float4*)Wl1 + idx);
    }
    CP_COMMIT();                                      // C3

    if (kh == 1) {
#pragma unroll
        for (int row = 0; row < 8; ++row)
            *(ulonglong2*)&P0[(r0 + row) * 64 + lane * 2] =
                make_ulonglong2(acc[row][0], acc[row][1]);
    }
    if (kh == 3) {
#pragma unroll
        for (int row = 0; row < 8; ++row)
            *(ulonglong2*)&P1s1[(r0 + row) * 64 + lane * 2] =
                make_ulonglong2(acc[row][0], acc[row][1]);
    }
    __syncthreads();
    if (kh == 2) {
#pragma unroll
        for (int row = 0; row < 8; ++row) {
            ulonglong2 q = *(ulonglong2*)&P1s1[(r0 + row) * 64 + lane * 2];
            add2(acc[row][0], q.x); add2(acc[row][1], q.y);
            *(ulonglong2*)&P1s1[(r0 + row) * 64 + lane * 2] =
                make_ulonglong2(acc[row][0], acc[row][1]);
        }
    }
    if (kh == 0) {
#pragma unroll
        for (int row = 0; row < 8; ++row) {
            ulonglong2 q = *(ulonglong2*)&P0[(r0 + row) * 64 + lane * 2];
            add2(acc[row][0], q.x); add2(acc[row][1], q.y);
        }
    }
    __syncthreads();
    if (kh == 0) {
#pragma unroll
        for (int row = 0; row < 8; ++row) {
            ulonglong2 q = *(ulonglong2*)&P1s1[(r0 + row) * 64 + lane * 2];
            add2(acc[row][0], q.x); add2(acc[row][1], q.y);
            *(ulonglong2*)&h0pair[(r0 + row) * 64 + lane * 2] =
                make_ulonglong2(acc[row][0], acc[row][1]);
            float2 a = unpk(acc[row][0]), b = unpk(acc[row][1]);
            h0dup[(r0 + row) * 128 + c0 + 0] = pk2(a.x);
            h0dup[(r0 + row) * 128 + c0 + 1] = pk2(a.y);
            h0dup[(r0 + row) * 128 + c0 + 2] = pk2(b.x);
            h0dup[(r0 + row) * 128 + c0 + 3] = pk2(b.y);
        }
    }
    CP_WAIT(1);            // wl0 done
    __syncthreads();

    // ================= stage 2: h1 = relu(h0 @ Wl0 + bl0) =================
    mlp_compute<32>(wl0f, h0dup, 128, kh * 32, r0, c0, acc);
    __syncthreads();                                  // h0dup dead now

    // stage wl1 d96..127: 32*128 floats = 1024 f4 -> [49152,65536)
#pragma unroll
    for (int i = 0; i < 2; ++i) {
        int idx = t + i * 512;                        // < 1024
        cp16(sb + 49152 + idx * 16, (const float4*)Wl1 + 3072 + idx);
    }
    CP_COMMIT();                                      // C4

    if (kh == 1) {
#pragma unroll
        for (int row = 0; row < 8; ++row)
            *(ulonglong2*)&P0[(r0 + row) * 64 + lane * 2] =
                make_ulonglong2(acc[row][0], acc[row][1]);
    }
    if (kh == 3) {
#pragma unroll
        for (int row = 0; row < 8; ++row)
            *(ulonglong2*)&P1s2[(r0 + row) * 64 + lane * 2] =
                make_ulonglong2(acc[row][0], acc[row][1]);
    }
    __syncthreads();
    if (kh == 2) {
#pragma unroll
        for (int row = 0; row < 8; ++row) {
            ulonglong2 q = *(ulonglong2*)&P1s2[(r0 + row) * 64 + lane * 2];
            add2(acc[row][0], q.x); add2(acc[row][1], q.y);
            *(ulonglong2*)&P1s2[(r0 + row) * 64 + lane * 2] =
                make_ulonglong2(acc[row][0], acc[row][1]);
        }
    }
    if (kh == 0) {
#pragma unroll
        for (int row = 0; row < 8; ++row) {
            ulonglong2 q = *(ulonglong2*)&P0[(r0 + row) * 64 + lane * 2];
            add2(acc[row][0], q.x); add2(acc[row][1], q.y);
        }
    }
    __syncthreads();
    if (kh == 0) {
        u64 bv0 = *(const u64*)&bl0[c0];
        u64 bv1 = *(const u64*)&bl0[c0 + 2];
#pragma unroll
        for (int row = 0; row < 8; ++row) {
            ulonglong2 q = *(ulonglong2*)&P1s2[(r0 + row) * 64 + lane * 2];
            add2(acc[row][0], q.x); add2(acc[row][1], q.y);
            add2(acc[row][0], bv0); add2(acc[row][1], bv1);
            float2 a = unpk(acc[row][0]), b = unpk(acc[row][1]);
            a.x = fmaxf(a.x, 0.f); a.y = fmaxf(a.y, 0.f);
            b.x = fmaxf(b.x, 0.f); b.y = fmaxf(b.y, 0.f);
            h1dup[(r0 + row) * 128 + c0 + 0] = pk2(a.x);
            h1dup[(r0 + row) * 128 + c0 + 1] = pk2(a.y);
            h1dup[(r0 + row) * 128 + c0 + 2] = pk2(b.x);
            h1dup[(r0 + row) * 128 + c0 + 3] = pk2(b.y);
        }
    }
    CP_WAIT(0);            // all wl1 staged
    __syncthreads();

    // ================= stage 3: out = h0 + relu(h1 @ Wl1 + bl1) ============
    mlp_compute<32>(wl1f, h1dup, 128, kh * 32, r0, c0, acc);
    __syncthreads();

    if (kh == 1) {
#pragma unroll
        for (int row = 0; row < 8; ++row)
            *(ulonglong2*)&P0[(r0 + row) * 64 + lane * 2] =
                make_ulonglong2(acc[row][0], acc[row][1]);
    }
    if (kh == 3) {
#pragma unroll
        for (int row = 0; row < 8; ++row)
            *(ulonglong2*)&P1s3[(r0 + row) * 64 + lane * 2] =
                make_ulonglong2(acc[row][0], acc[row][1]);
    }
    __syncthreads();
    if (kh == 2) {
#pragma unroll
        for (int row = 0; row < 8; ++row) {
            ulonglong2 q = *(ulonglong2*)&P1s3[(r0 + row) * 64 + lane * 2];
            add2(acc[row][0], q.x); add2(acc[row][1], q.y);
            *(ulonglong2*)&P1s3[(r0 + row) * 64 + lane * 2] =
                make_ulonglong2(acc[row][0], acc[row][1]);
        }
    }
    if (kh == 0) {
#pragma unroll
        for (int row = 0; row < 8; ++row) {
            ulonglong2 q = *(ulonglong2*)&P0[(r0 + row) * 64 + lane * 2];
            add2(acc[row][0], q.x); add2(acc[row][1], q.y);
        }
    }
    __syncthreads();
    if (kh == 0) {
        u64 bv0 = *(const u64*)&bl1[c0];
        u64 bv1 = *(const u64*)&bl1[c0 + 2];
#pragma unroll
        for (int row = 0; row < 8; ++row) {
            ulonglong2 q = *(ulonglong2*)&P1s3[(r0 + row) * 64 + lane * 2];
            add2(acc[row][0], q.x); add2(acc[row][1], q.y);
            add2(acc[row][0], bv0); add2(acc[row][1], bv1);
            float2 a = unpk(acc[row][0]), b = unpk(acc[row][1]);
            u64 o0 = pkpair(fmaxf(a.x, 0.f), fmaxf(a.y, 0.f));
            u64 o1 = pkpair(fmaxf(b.x, 0.f), fmaxf(b.y, 0.f));
            ulonglong2 hp = *(ulonglong2*)&h0pair[(r0 + row) * 64 + lane * 2];
            add2(o0, hp.x); add2(o1, hp.y);
            *(ulonglong2*)&out[(size_t)(row0 + r0 + row) * 128 + c0] =
                make_ulonglong2(o0, o1);
        }
    }
}

// ---------------------------------------------------------------------------
extern "C" void kernel_launch(void* const* d_in, const int* in_sizes, int n_in,
                              void* d_out, int out_size) {
    const float* seqs = (const float*)d_in[0];
    const float* W2   = (const float*)d_in[3];
    const float* p    = (const float*)d_in[6];
    const float* Wq   = (const float*)d_in[7];
    const float* Wl0  = (const float*)d_in[8];
    const float* bl0  = (const float*)d_in[9];
    const float* Wl1  = (const float*)d_in[10];
    const float* bl1  = (const float*)d_in[11];
    float* out = (float*)d_out;

    static bool init_done = false;
    if (!init_done) {
        cudaFuncSetAttribute(mlp_kernel,
                             cudaFuncAttributeMaxDynamicSharedMemorySize, 212992);
        init_done = true;
    }

    attn_kernel<<<NG / 2, 256>>>(seqs, W2, p);
    mlp_kernel<<<NG / 32, 512, 212992>>>(Wq, Wl0, bl0, Wl1, bl1, out);
}